// round 3
// baseline (speedup 1.0000x reference)
#include <cuda_runtime.h>
#include <cuda_bf16.h>
#include <cstdint>

#define HW     9216
#define IMG_W  96
#define IMG_H  96
#define CCH    192
#define NB     4

// Scratch buffers (no cudaMalloc allowed)
__device__ __nv_bfloat16 g_xT_hi[(size_t)NB * HW * CCH];
__device__ __nv_bfloat16 g_xT_lo[(size_t)NB * HW * CCH];
__device__ float         g_qkv  [(size_t)NB * HW * 3 * CCH];
__device__ __nv_bfloat16 g_at_hi[(size_t)NB * HW * CCH];
__device__ __nv_bfloat16 g_at_lo[(size_t)NB * HW * CCH];
__device__ __nv_bfloat16 g_w_hi [(576 + 192) * CCH];   // w_qkv then w_out
__device__ __nv_bfloat16 g_w_lo [(576 + 192) * CCH];

__device__ __forceinline__ void bfsplit(float a, __nv_bfloat16& h, __nv_bfloat16& l) {
    h = __float2bfloat16_rn(a);
    l = __float2bfloat16_rn(a - __bfloat162float(h));
}
__device__ __forceinline__ uint32_t pack2(__nv_bfloat16 a, __nv_bfloat16 b) {
    return ((uint32_t)__bfloat16_as_ushort(b) << 16) | __bfloat16_as_ushort(a);
}

// ============================================================================
// Weight prep: split fp32 weights into bf16 hi/lo
// ============================================================================
__global__ void prep_weights(const float* __restrict__ w_qkv,
                             const float* __restrict__ w_out) {
    const int i = blockIdx.x * 256 + threadIdx.x;   // over 768*192 elems
    const int total = (576 + 192) * CCH;
    if (i >= total) return;
    const float v = (i < 576 * CCH) ? w_qkv[i] : w_out[i - 576 * CCH];
    bfsplit(v, g_w_hi[i], g_w_lo[i]);
}

// ============================================================================
// Transpose + split: x[b][192][HW] fp32 -> xT_hi/lo[b][HW][192] bf16
// ============================================================================
__global__ void transpose_k(const float* __restrict__ x) {
    __shared__ float tile[32][33];
    const int b  = blockIdx.z;
    const int p0 = blockIdx.x * 32, c0 = blockIdx.y * 32;
    const float* xb = x + (size_t)b * CCH * HW;
    __nv_bfloat16* th = g_xT_hi + (size_t)b * HW * CCH;
    __nv_bfloat16* tl = g_xT_lo + (size_t)b * HW * CCH;
    const int tx = threadIdx.x, ty = threadIdx.y;
    #pragma unroll
    for (int j = 0; j < 32; j += 8)
        tile[ty + j][tx] = xb[(size_t)(c0 + ty + j) * HW + p0 + tx];
    __syncthreads();
    #pragma unroll
    for (int j = 0; j < 32; j += 8) {
        const size_t o = (size_t)(p0 + ty + j) * CCH + c0 + tx;
        bfsplit(tile[tx][ty + j], th[o], tl[o]);
    }
}

// ============================================================================
// bf16x3 split GEMM via mma.sync.m16n8k16:
//   C[m][n] = sum_k A[m][k]*B[n][k],  A: [M][192] bf16 hi/lo (per-batch),
//   B: [Ntot][192] bf16 hi/lo (shared). Tile M=128, N=64, K staged 3x64.
//   8 warps: warp tile 32x32 (wm = wid%4, wn = wid/4).
//   TRANS=0: C fp32 [m][Ntot];  TRANS=1: C fp32 [n][HW] (channel-major).
// ============================================================================
#define RS   144                        // smem row stride bytes (72 bf16)
#define SM_AH 0
#define SM_AL (SM_AH + 128 * RS)        // 18432
#define SM_BH (SM_AL + 128 * RS)        // 36864
#define SM_BL (SM_BH +  64 * RS)        // 46080
#define SM_GTOT (SM_BL + 64 * RS)       // 55296

__device__ __forceinline__ void mma16816(float* c, const uint32_t* a, const uint32_t* b) {
    asm volatile(
        "mma.sync.aligned.m16n8k16.row.col.f32.bf16.bf16.f32 "
        "{%0,%1,%2,%3}, {%4,%5,%6,%7}, {%8,%9}, {%0,%1,%2,%3};"
        : "+f"(c[0]), "+f"(c[1]), "+f"(c[2]), "+f"(c[3])
        : "r"(a[0]), "r"(a[1]), "r"(a[2]), "r"(a[3]), "r"(b[0]), "r"(b[1]));
}

template<int TRANS>
__global__ __launch_bounds__(256, 2)
void mma_gemm(const __nv_bfloat16* __restrict__ Ah,
              const __nv_bfloat16* __restrict__ Al,
              const __nv_bfloat16* __restrict__ Bh,
              const __nv_bfloat16* __restrict__ Bl,
              float* __restrict__ C, int Ntot,
              size_t strideA, size_t strideC)
{
    extern __shared__ char smem[];
    const int t   = threadIdx.x;
    const int wid = t >> 5, lane = t & 31;
    const int gid = lane >> 2, tig = lane & 3;
    const int wm  = wid & 3, wn = wid >> 2;
    const int m0  = blockIdx.y * 128;
    const int n0  = blockIdx.x * 64;

    const __nv_bfloat16* Abh = Ah + (size_t)blockIdx.z * strideA + (size_t)m0 * CCH;
    const __nv_bfloat16* Abl = Al + (size_t)blockIdx.z * strideA + (size_t)m0 * CCH;
    float* Cb = C + (size_t)blockIdx.z * strideC;

    float acc[2][4][4];
    #pragma unroll
    for (int mi = 0; mi < 2; mi++)
        #pragma unroll
        for (int ni = 0; ni < 4; ni++)
            #pragma unroll
            for (int j = 0; j < 4; j++) acc[mi][ni][j] = 0.f;

    #pragma unroll 1
    for (int s = 0; s < 3; s++) {
        const int k0 = s * 64;
        // A tile: 128 rows x 64 cols, 8-bf16 chunks; 1024 chunks / 256 thr = 4
        #pragma unroll
        for (int i = 0; i < 4; i++) {
            const int idx = t + i * 256;
            const int row = idx >> 3, c8 = (idx & 7) * 8;
            const size_t go = (size_t)row * CCH + k0 + c8;
            const uint32_t so = row * RS + c8 * 2;
            *(uint4*)(smem + SM_AH + so) = *(const uint4*)(Abh + go);
            *(uint4*)(smem + SM_AL + so) = *(const uint4*)(Abl + go);
        }
        // B tile: 64 rows x 64 cols; 512 chunks / 256 thr = 2
        #pragma unroll
        for (int i = 0; i < 2; i++) {
            const int idx = t + i * 256;
            const int row = idx >> 3, c8 = (idx & 7) * 8;
            const size_t go = (size_t)(n0 + row) * CCH + k0 + c8;
            const uint32_t so = row * RS + c8 * 2;
            *(uint4*)(smem + SM_BH + so) = *(const uint4*)(Bh + go);
            *(uint4*)(smem + SM_BL + so) = *(const uint4*)(Bl + go);
        }
        __syncthreads();

        #pragma unroll
        for (int kk = 0; kk < 4; kk++) {
            const uint32_t cb = kk * 32 + tig * 4;     // col byte offset
            uint32_t ah[2][4], al[2][4], bh[4][2], bl[4][2];
            #pragma unroll
            for (int mi = 0; mi < 2; mi++) {
                const uint32_t r0 = (wm * 32 + mi * 16 + gid) * RS + cb;
                ah[mi][0] = *(const uint32_t*)(smem + SM_AH + r0);
                ah[mi][1] = *(const uint32_t*)(smem + SM_AH + r0 + 8 * RS);
                ah[mi][2] = *(const uint32_t*)(smem + SM_AH + r0 + 16);
                ah[mi][3] = *(const uint32_t*)(smem + SM_AH + r0 + 8 * RS + 16);
                al[mi][0] = *(const uint32_t*)(smem + SM_AL + r0);
                al[mi][1] = *(const uint32_t*)(smem + SM_AL + r0 + 8 * RS);
                al[mi][2] = *(const uint32_t*)(smem + SM_AL + r0 + 16);
                al[mi][3] = *(const uint32_t*)(smem + SM_AL + r0 + 8 * RS + 16);
            }
            #pragma unroll
            for (int ni = 0; ni < 4; ni++) {
                const uint32_t rn = (wn * 32 + ni * 8 + gid) * RS + cb;
                bh[ni][0] = *(const uint32_t*)(smem + SM_BH + rn);
                bh[ni][1] = *(const uint32_t*)(smem + SM_BH + rn + 16);
                bl[ni][0] = *(const uint32_t*)(smem + SM_BL + rn);
                bl[ni][1] = *(const uint32_t*)(smem + SM_BL + rn + 16);
            }
            #pragma unroll
            for (int mi = 0; mi < 2; mi++)
                #pragma unroll
                for (int ni = 0; ni < 4; ni++) {
                    mma16816(acc[mi][ni], ah[mi], bh[ni]);
                    mma16816(acc[mi][ni], ah[mi], bl[ni]);
                    mma16816(acc[mi][ni], al[mi], bh[ni]);
                }
        }
        __syncthreads();
    }

    // Epilogue. C frag: c0,c1 = (row gid, cols 2tig,2tig+1); c2,c3 = row gid+8.
    #pragma unroll
    for (int mi = 0; mi < 2; mi++) {
        const int row = m0 + wm * 32 + mi * 16 + gid;
        #pragma unroll
        for (int ni = 0; ni < 4; ni++) {
            const int col = n0 + wn * 32 + ni * 8 + 2 * tig;
            if (TRANS == 0) {
                *(float2*)&Cb[(size_t)row * Ntot + col] =
                    make_float2(acc[mi][ni][0], acc[mi][ni][1]);
                *(float2*)&Cb[(size_t)(row + 8) * Ntot + col] =
                    make_float2(acc[mi][ni][2], acc[mi][ni][3]);
            } else {
                Cb[(size_t)col       * HW + row]     = acc[mi][ni][0];
                Cb[(size_t)(col + 1) * HW + row]     = acc[mi][ni][1];
                Cb[(size_t)col       * HW + row + 8] = acc[mi][ni][2];
                Cb[(size_t)(col + 1) * HW + row + 8] = acc[mi][ni][3];
            }
        }
    }
}

// ============================================================================
// Neighborhood attention, pixel-major, float4 loads; writes bf16 hi/lo.
// qkv row per pixel: [q 0..191 | k 192..383 | v 384..575]
// ============================================================================
template<int K, int DIL>
__device__ __forceinline__ void natt_body(const float* __restrict__ bias,
                                          int head, int b)
{
    const int w   = blockIdx.x * 32 + threadIdx.x;
    const int h   = blockIdx.y * 4  + threadIdx.y;
    const int pix = h * IMG_W + w;

    const float* base = g_qkv + (size_t)b * HW * 576;
    const float* qp   = base + (size_t)pix * 576 + head * 32;

    float4 q[8];
    #pragma unroll
    for (int i = 0; i < 8; i++) q[i] = ((const float4*)qp)[i];

    float4 acc[8];
    #pragma unroll
    for (int i = 0; i < 8; i++) acc[i] = make_float4(0.f, 0.f, 0.f, 0.f);
    float l = 0.f;
    const float scale = 0.17677669529663689f;  // 1/sqrt(32)

    #pragma unroll 1
    for (int di = 0; di < K; di++) {
        const int hh = h + (di - K / 2) * DIL;
        const bool rok = ((unsigned)hh < IMG_H);
        #pragma unroll
        for (int dj = 0; dj < K; dj++) {
            const int ww = w + (dj - K / 2) * DIL;
            const bool ok = rok && ((unsigned)ww < IMG_W);
            const int off = hh * IMG_W + ww;
            const float* kp = base + (size_t)off * 576 + 192 + head * 32;
            float s = 0.f;
            if (ok) {
                #pragma unroll
                for (int i = 0; i < 8; i++) {
                    float4 kv = ((const float4*)kp)[i];
                    s += q[i].x * kv.x + q[i].y * kv.y
                       + q[i].z * kv.z + q[i].w * kv.w;
                }
            }
            const float e = __expf(s * scale + __ldg(&bias[di * K + dj]));
            l += e;
            if (ok) {
                const float* vp = kp + 192;
                #pragma unroll
                for (int i = 0; i < 8; i++) {
                    float4 vv = ((const float4*)vp)[i];
                    acc[i].x += e * vv.x; acc[i].y += e * vv.y;
                    acc[i].z += e * vv.z; acc[i].w += e * vv.w;
                }
            }
        }
    }

    const float il = 1.f / l;
    const size_t ob = ((size_t)b * HW + pix) * CCH + head * 32;
    #pragma unroll
    for (int i = 0; i < 8; i++) {
        float v0 = acc[i].x * il, v1 = acc[i].y * il;
        float v2 = acc[i].z * il, v3 = acc[i].w * il;
        __nv_bfloat16 h0, h1, h2, h3, l0, l1, l2, l3;
        bfsplit(v0, h0, l0); bfsplit(v1, h1, l1);
        bfsplit(v2, h2, l2); bfsplit(v3, h3, l3);
        *(uint32_t*)&g_at_hi[ob + i * 4]     = pack2(h0, h1);
        *(uint32_t*)&g_at_hi[ob + i * 4 + 2] = pack2(h2, h3);
        *(uint32_t*)&g_at_lo[ob + i * 4]     = pack2(l0, l1);
        *(uint32_t*)&g_at_lo[ob + i * 4 + 2] = pack2(l2, l3);
    }
}

__global__ __launch_bounds__(128)
void natt_all(const float* __restrict__ b0, const float* __restrict__ b1,
              const float* __restrict__ b2, const float* __restrict__ b3,
              const float* __restrict__ b4, const float* __restrict__ b5)
{
    const int z = blockIdx.z;
    const int head = z % 6;
    const int b    = z / 6;
    switch (head) {
        case 0: natt_body<3, 1>(b0, 0, b); break;
        case 1: natt_body<5, 2>(b1, 1, b); break;
        case 2: natt_body<7, 1>(b2, 2, b); break;
        case 3: natt_body<7, 3>(b3, 3, b); break;
        case 4: natt_body<9, 1>(b4, 4, b); break;
        case 5: natt_body<9, 2>(b5, 5, b); break;
    }
}

// ============================================================================
extern "C" void kernel_launch(void* const* d_in, const int* in_sizes, int n_in,
                              void* d_out, int out_size)
{
    (void)in_sizes; (void)n_in; (void)out_size;
    const float* x     = (const float*)d_in[0];
    const float* w_qkv = (const float*)d_in[1];
    const float* w_out = (const float*)d_in[2];
    const float* b0 = (const float*)d_in[3];
    const float* b1 = (const float*)d_in[4];
    const float* b2 = (const float*)d_in[5];
    const float* b3 = (const float*)d_in[6];
    const float* b4 = (const float*)d_in[7];
    const float* b5 = (const float*)d_in[8];

    __nv_bfloat16 *xh, *xl, *ah, *al, *wh, *wl;
    float *qkv;
    cudaGetSymbolAddress((void**)&xh,  g_xT_hi);
    cudaGetSymbolAddress((void**)&xl,  g_xT_lo);
    cudaGetSymbolAddress((void**)&ah,  g_at_hi);
    cudaGetSymbolAddress((void**)&al,  g_at_lo);
    cudaGetSymbolAddress((void**)&wh,  g_w_hi);
    cudaGetSymbolAddress((void**)&wl,  g_w_lo);
    cudaGetSymbolAddress((void**)&qkv, g_qkv);

    cudaFuncSetAttribute(mma_gemm<0>, cudaFuncAttributeMaxDynamicSharedMemorySize, SM_GTOT);
    cudaFuncSetAttribute(mma_gemm<1>, cudaFuncAttributeMaxDynamicSharedMemorySize, SM_GTOT);

    prep_weights<<<(768 * CCH + 255) / 256, 256>>>(w_qkv, w_out);
    transpose_k<<<dim3(HW / 32, CCH / 32, NB), dim3(32, 8)>>>(x);

    // qkv[pix][576] = xT @ w_qkv^T
    mma_gemm<0><<<dim3(576 / 64, HW / 128, NB), 256, SM_GTOT>>>(
        xh, xl, wh, wl, qkv, 576, (size_t)HW * CCH, (size_t)HW * 576);

    natt_all<<<dim3(IMG_W / 32, IMG_H / 4, NB * 6), dim3(32, 4)>>>(
        b0, b1, b2, b3, b4, b5);

    // out[ch][pix] = (attn @ w_out^T)^T
    mma_gemm<1><<<dim3(CCH / 64, HW / 128, NB), 256, SM_GTOT>>>(
        ah, al, wh + 576 * CCH, wl + 576 * CCH, (float*)d_out, CCH,
        (size_t)HW * CCH, (size_t)CCH * HW);
}

// round 5
// speedup vs baseline: 2.4931x; 2.4931x over previous
#include <cuda_runtime.h>
#include <cuda_bf16.h>
#include <cstdint>

#define HW     9216
#define IMG_W  96
#define IMG_H  96
#define CCH    192
#define NB     4

// Scratch buffers (no cudaMalloc allowed)
__device__ __nv_bfloat16 g_xT_hi[(size_t)NB * HW * CCH];
__device__ __nv_bfloat16 g_xT_lo[(size_t)NB * HW * CCH];
// qkv in d4-packed layout: [b][576/4][HW][4] fp32
__device__ float         g_qkv  [(size_t)NB * HW * 3 * CCH];
__device__ __nv_bfloat16 g_at_hi[(size_t)NB * HW * CCH];
__device__ __nv_bfloat16 g_at_lo[(size_t)NB * HW * CCH];
__device__ __nv_bfloat16 g_w_hi [(576 + 192) * CCH];   // w_qkv then w_out
__device__ __nv_bfloat16 g_w_lo [(576 + 192) * CCH];

__device__ __forceinline__ void bfsplit(float a, __nv_bfloat16& h, __nv_bfloat16& l) {
    h = __float2bfloat16_rn(a);
    l = __float2bfloat16_rn(a - __bfloat162float(h));
}
__device__ __forceinline__ uint32_t pack2(__nv_bfloat16 a, __nv_bfloat16 b) {
    return ((uint32_t)__bfloat16_as_ushort(b) << 16) | __bfloat16_as_ushort(a);
}

// ============================================================================
// Weight prep: split fp32 weights into bf16 hi/lo
// ============================================================================
__global__ void prep_weights(const float* __restrict__ w_qkv,
                             const float* __restrict__ w_out) {
    const int i = blockIdx.x * 256 + threadIdx.x;
    const int total = (576 + 192) * CCH;
    if (i >= total) return;
    const float v = (i < 576 * CCH) ? w_qkv[i] : w_out[i - 576 * CCH];
    bfsplit(v, g_w_hi[i], g_w_lo[i]);
}

// ============================================================================
// Transpose + split: x[b][192][HW] fp32 -> xT_hi/lo[b][HW][192] bf16
// ============================================================================
__global__ void transpose_k(const float* __restrict__ x) {
    __shared__ float tile[32][33];
    const int b  = blockIdx.z;
    const int p0 = blockIdx.x * 32, c0 = blockIdx.y * 32;
    const float* xb = x + (size_t)b * CCH * HW;
    __nv_bfloat16* th = g_xT_hi + (size_t)b * HW * CCH;
    __nv_bfloat16* tl = g_xT_lo + (size_t)b * HW * CCH;
    const int tx = threadIdx.x, ty = threadIdx.y;
    #pragma unroll
    for (int j = 0; j < 32; j += 8)
        tile[ty + j][tx] = xb[(size_t)(c0 + ty + j) * HW + p0 + tx];
    __syncthreads();
    #pragma unroll
    for (int j = 0; j < 32; j += 8) {
        const size_t o = (size_t)(p0 + ty + j) * CCH + c0 + tx;
        bfsplit(tile[tx][ty + j], th[o], tl[o]);
    }
}

// ============================================================================
// bf16x3 split GEMM via mma.sync.m16n8k16:
//   C[m][n] = sum_k A[m][k]*B[n][k],  A: [M][192] bf16 hi/lo (per-batch),
//   B: [Ntot][192] bf16 hi/lo. Tile M=128, N=64, K staged 3x64, 8 warps.
//   MODE=1: C fp32 [n][HW] channel-major (d_out).
//   MODE=2: C fp32 d4-packed [n/4][HW][4] (qkv).
// ============================================================================
#define RS   144                        // smem row stride bytes (72 bf16)
#define SM_AH 0
#define SM_AL (SM_AH + 128 * RS)
#define SM_BH (SM_AL + 128 * RS)
#define SM_BL (SM_BH +  64 * RS)
#define SM_GTOT (SM_BL + 64 * RS)       // 55296

__device__ __forceinline__ void mma16816(float* c, const uint32_t* a, const uint32_t* b) {
    asm volatile(
        "mma.sync.aligned.m16n8k16.row.col.f32.bf16.bf16.f32 "
        "{%0,%1,%2,%3}, {%4,%5,%6,%7}, {%8,%9}, {%0,%1,%2,%3};"
        : "+f"(c[0]), "+f"(c[1]), "+f"(c[2]), "+f"(c[3])
        : "r"(a[0]), "r"(a[1]), "r"(a[2]), "r"(a[3]), "r"(b[0]), "r"(b[1]));
}

template<int MODE>
__global__ __launch_bounds__(256, 2)
void mma_gemm(const __nv_bfloat16* __restrict__ Ah,
              const __nv_bfloat16* __restrict__ Al,
              const __nv_bfloat16* __restrict__ Bh,
              const __nv_bfloat16* __restrict__ Bl,
              float* __restrict__ C,
              size_t strideA, size_t strideC)
{
    extern __shared__ char smem[];
    const int t   = threadIdx.x;
    const int wid = t >> 5, lane = t & 31;
    const int gid = lane >> 2, tig = lane & 3;
    const int wm  = wid & 3, wn = wid >> 2;
    const int m0  = blockIdx.y * 128;
    const int n0  = blockIdx.x * 64;

    const __nv_bfloat16* Abh = Ah + (size_t)blockIdx.z * strideA + (size_t)m0 * CCH;
    const __nv_bfloat16* Abl = Al + (size_t)blockIdx.z * strideA + (size_t)m0 * CCH;
    float* Cb = C + (size_t)blockIdx.z * strideC;

    float acc[2][4][4];
    #pragma unroll
    for (int mi = 0; mi < 2; mi++)
        #pragma unroll
        for (int ni = 0; ni < 4; ni++)
            #pragma unroll
            for (int j = 0; j < 4; j++) acc[mi][ni][j] = 0.f;

    #pragma unroll 1
    for (int s = 0; s < 3; s++) {
        const int k0 = s * 64;
        #pragma unroll
        for (int i = 0; i < 4; i++) {
            const int idx = t + i * 256;
            const int row = idx >> 3, c8 = (idx & 7) * 8;
            const size_t go = (size_t)row * CCH + k0 + c8;
            const uint32_t so = row * RS + c8 * 2;
            *(uint4*)(smem + SM_AH + so) = *(const uint4*)(Abh + go);
            *(uint4*)(smem + SM_AL + so) = *(const uint4*)(Abl + go);
        }
        #pragma unroll
        for (int i = 0; i < 2; i++) {
            const int idx = t + i * 256;
            const int row = idx >> 3, c8 = (idx & 7) * 8;
            const size_t go = (size_t)(n0 + row) * CCH + k0 + c8;
            const uint32_t so = row * RS + c8 * 2;
            *(uint4*)(smem + SM_BH + so) = *(const uint4*)(Bh + go);
            *(uint4*)(smem + SM_BL + so) = *(const uint4*)(Bl + go);
        }
        __syncthreads();

        #pragma unroll
        for (int kk = 0; kk < 4; kk++) {
            const uint32_t cb = kk * 32 + tig * 4;
            uint32_t ah[2][4], al[2][4], bh[4][2], bl[4][2];
            #pragma unroll
            for (int mi = 0; mi < 2; mi++) {
                const uint32_t r0 = (wm * 32 + mi * 16 + gid) * RS + cb;
                ah[mi][0] = *(const uint32_t*)(smem + SM_AH + r0);
                ah[mi][1] = *(const uint32_t*)(smem + SM_AH + r0 + 8 * RS);
                ah[mi][2] = *(const uint32_t*)(smem + SM_AH + r0 + 16);
                ah[mi][3] = *(const uint32_t*)(smem + SM_AH + r0 + 8 * RS + 16);
                al[mi][0] = *(const uint32_t*)(smem + SM_AL + r0);
                al[mi][1] = *(const uint32_t*)(smem + SM_AL + r0 + 8 * RS);
                al[mi][2] = *(const uint32_t*)(smem + SM_AL + r0 + 16);
                al[mi][3] = *(const uint32_t*)(smem + SM_AL + r0 + 8 * RS + 16);
            }
            #pragma unroll
            for (int ni = 0; ni < 4; ni++) {
                const uint32_t rn = (wn * 32 + ni * 8 + gid) * RS + cb;
                bh[ni][0] = *(const uint32_t*)(smem + SM_BH + rn);
                bh[ni][1] = *(const uint32_t*)(smem + SM_BH + rn + 16);
                bl[ni][0] = *(const uint32_t*)(smem + SM_BL + rn);
                bl[ni][1] = *(const uint32_t*)(smem + SM_BL + rn + 16);
            }
            #pragma unroll
            for (int mi = 0; mi < 2; mi++)
                #pragma unroll
                for (int ni = 0; ni < 4; ni++) {
                    mma16816(acc[mi][ni], ah[mi], bh[ni]);
                    mma16816(acc[mi][ni], ah[mi], bl[ni]);
                    mma16816(acc[mi][ni], al[mi], bh[ni]);
                }
        }
        __syncthreads();
    }

    // Epilogue. Frag rows: gid, gid+8; cols: 2tig, 2tig+1 (col even).
    #pragma unroll
    for (int mi = 0; mi < 2; mi++) {
        const int row = m0 + wm * 32 + mi * 16 + gid;
        #pragma unroll
        for (int ni = 0; ni < 4; ni++) {
            const int col = n0 + wn * 32 + ni * 8 + 2 * tig;
            if (MODE == 1) {          // channel-major [col][HW]
                Cb[(size_t)col       * HW + row]     = acc[mi][ni][0];
                Cb[(size_t)(col + 1) * HW + row]     = acc[mi][ni][1];
                Cb[(size_t)col       * HW + row + 8] = acc[mi][ni][2];
                Cb[(size_t)(col + 1) * HW + row + 8] = acc[mi][ni][3];
            } else {                  // d4-packed [col/4][HW][4]
                const int pg = col >> 2, ln = col & 3;   // ln in {0,2}
                *(float2*)&Cb[((size_t)pg * HW + row)     * 4 + ln] =
                    make_float2(acc[mi][ni][0], acc[mi][ni][1]);
                *(float2*)&Cb[((size_t)pg * HW + row + 8) * 4 + ln] =
                    make_float2(acc[mi][ni][2], acc[mi][ni][3]);
            }
        }
    }
}

// ============================================================================
// Neighborhood attention over d4-packed qkv.
//   qkv layout: [b][pg 0..143][pix][4]; head i: q pg = i*8.., k pg = 48+i*8..,
//   v pg = 96+i*8.. Each warp lane = consecutive w -> LDG.128 fully coalesced.
//   Output: pixel-major bf16 hi/lo for GEMM2.
// ============================================================================
template<int K, int DIL>
__device__ __forceinline__ void natt_body(const float* __restrict__ sbias,
                                          int head, int b)
{
    const int w   = blockIdx.x * 32 + threadIdx.x;
    const int h   = blockIdx.y * 4  + threadIdx.y;
    const int pix = h * IMG_W + w;

    const float* base = g_qkv + (size_t)b * 576 * HW;
    const float* qp = base + ((size_t)(head * 8) * HW + pix) * 4;
    const float* kb = base + ((size_t)(48 + head * 8) * HW) * 4;
    const float* vb = base + ((size_t)(96 + head * 8) * HW) * 4;
    const float scale = 0.17677669529663689f;  // 1/sqrt(32)

    float4 q[8];
    #pragma unroll
    for (int i = 0; i < 8; i++) {
        float4 t = *(const float4*)(qp + (size_t)i * HW * 4);
        q[i] = make_float4(t.x * scale, t.y * scale, t.z * scale, t.w * scale);
    }

    float4 acc[8];
    #pragma unroll
    for (int i = 0; i < 8; i++) acc[i] = make_float4(0.f, 0.f, 0.f, 0.f);
    float l = 0.f;

    #pragma unroll 1
    for (int di = 0; di < K; di++) {
        const int hh = h + (di - K / 2) * DIL;
        const bool rok = ((unsigned)hh < IMG_H);
        #pragma unroll
        for (int dj = 0; dj < K; dj++) {
            const int ww = w + (dj - K / 2) * DIL;
            const bool ok = rok && ((unsigned)ww < IMG_W);
            const int off = hh * IMG_W + ww;
            float s = 0.f;
            if (ok) {
                const float* kp = kb + (size_t)off * 4;
                #pragma unroll
                for (int i = 0; i < 8; i++) {
                    float4 kv = *(const float4*)(kp + (size_t)i * HW * 4);
                    s += q[i].x * kv.x + q[i].y * kv.y
                       + q[i].z * kv.z + q[i].w * kv.w;
                }
            }
            const float e = __expf(s + sbias[di * K + dj]);
            l += e;
            if (ok) {
                const float* vp = vb + (size_t)off * 4;
                #pragma unroll
                for (int i = 0; i < 8; i++) {
                    float4 vv = *(const float4*)(vp + (size_t)i * HW * 4);
                    acc[i].x += e * vv.x; acc[i].y += e * vv.y;
                    acc[i].z += e * vv.z; acc[i].w += e * vv.w;
                }
            }
        }
    }

    const float il = 1.f / l;
    const size_t ob = ((size_t)b * HW + pix) * CCH + head * 32;
    #pragma unroll
    for (int i = 0; i < 8; i++) {
        float v0 = acc[i].x * il, v1 = acc[i].y * il;
        float v2 = acc[i].z * il, v3 = acc[i].w * il;
        __nv_bfloat16 h0, h1, h2, h3, l0, l1, l2, l3;
        bfsplit(v0, h0, l0); bfsplit(v1, h1, l1);
        bfsplit(v2, h2, l2); bfsplit(v3, h3, l3);
        *(uint32_t*)&g_at_hi[ob + i * 4]     = pack2(h0, h1);
        *(uint32_t*)&g_at_hi[ob + i * 4 + 2] = pack2(h2, h3);
        *(uint32_t*)&g_at_lo[ob + i * 4]     = pack2(l0, l1);
        *(uint32_t*)&g_at_lo[ob + i * 4 + 2] = pack2(l2, l3);
    }
}

__global__ __launch_bounds__(128)
void natt_all(const float* __restrict__ b0, const float* __restrict__ b1,
              const float* __restrict__ b2, const float* __restrict__ b3,
              const float* __restrict__ b4, const float* __restrict__ b5)
{
    __shared__ float sb[81];
    const int z = blockIdx.z;
    const int head = z % 6;
    const int b    = z / 6;
    const float* bp;
    int k2;
    switch (head) {
        case 0: bp = b0; k2 = 9;  break;
        case 1: bp = b1; k2 = 25; break;
        case 2: bp = b2; k2 = 49; break;
        case 3: bp = b3; k2 = 49; break;
        case 4: bp = b4; k2 = 81; break;
        default: bp = b5; k2 = 81; break;
    }
    const int t = threadIdx.y * 32 + threadIdx.x;
    if (t < k2) sb[t] = bp[t];
    __syncthreads();
    switch (head) {
        case 0: natt_body<3, 1>(sb, 0, b); break;
        case 1: natt_body<5, 2>(sb, 1, b); break;
        case 2: natt_body<7, 1>(sb, 2, b); break;
        case 3: natt_body<7, 3>(sb, 3, b); break;
        case 4: natt_body<9, 1>(sb, 4, b); break;
        case 5: natt_body<9, 2>(sb, 5, b); break;
    }
}

// ============================================================================
extern "C" void kernel_launch(void* const* d_in, const int* in_sizes, int n_in,
                              void* d_out, int out_size)
{
    (void)in_sizes; (void)n_in; (void)out_size;
    const float* x     = (const float*)d_in[0];
    const float* w_qkv = (const float*)d_in[1];
    const float* w_out = (const float*)d_in[2];
    const float* b0 = (const float*)d_in[3];
    const float* b1 = (const float*)d_in[4];
    const float* b2 = (const float*)d_in[5];
    const float* b3 = (const float*)d_in[6];
    const float* b4 = (const float*)d_in[7];
    const float* b5 = (const float*)d_in[8];

    __nv_bfloat16 *xh, *xl, *ah, *al, *wh, *wl;
    float *qkv;
    cudaGetSymbolAddress((void**)&xh,  g_xT_hi);
    cudaGetSymbolAddress((void**)&xl,  g_xT_lo);
    cudaGetSymbolAddress((void**)&ah,  g_at_hi);
    cudaGetSymbolAddress((void**)&al,  g_at_lo);
    cudaGetSymbolAddress((void**)&wh,  g_w_hi);
    cudaGetSymbolAddress((void**)&wl,  g_w_lo);
    cudaGetSymbolAddress((void**)&qkv, g_qkv);

    cudaFuncSetAttribute(mma_gemm<1>, cudaFuncAttributeMaxDynamicSharedMemorySize, SM_GTOT);
    cudaFuncSetAttribute(mma_gemm<2>, cudaFuncAttributeMaxDynamicSharedMemorySize, SM_GTOT);

    prep_weights<<<(768 * CCH + 255) / 256, 256>>>(w_qkv, w_out);
    transpose_k<<<dim3(HW / 32, CCH / 32, NB), dim3(32, 8)>>>(x);

    // qkv (d4-packed) = xT @ w_qkv^T
    mma_gemm<2><<<dim3(576 / 64, HW / 128, NB), 256, SM_GTOT>>>(
        xh, xl, wh, wl, qkv, (size_t)HW * CCH, (size_t)HW * 576);

    natt_all<<<dim3(IMG_W / 32, IMG_H / 4, NB * 6), dim3(32, 4)>>>(
        b0, b1, b2, b3, b4, b5);

    // d_out (channel-major) = (attn @ w_out^T)^T
    mma_gemm<1><<<dim3(CCH / 64, HW / 128, NB), 256, SM_GTOT>>>(
        ah, al, wh + 576 * CCH, wl + 576 * CCH, (float*)d_out,
        (size_t)HW * CCH, (size_t)CCH * HW);
}

// round 6
// speedup vs baseline: 3.7004x; 1.4843x over previous
#include <cuda_runtime.h>
#include <cuda_fp16.h>
#include <cstdint>

#define HW     9216
#define IMG_W  96
#define IMG_H  96
#define CCH    192
#define NB     4

// Scratch (no cudaMalloc allowed)
__device__ __half g_x16[(size_t)NB * HW * CCH];          // [b][pix][192] fp16
__device__ __half g_w16[(576 + 192) * CCH];              // w_qkv then w_out, fp16
__device__ float  g_q  [(size_t)NB * HW * CCH];          // [b][48 pg][HW][4] fp32
__device__ __half g_k  [(size_t)NB * HW * CCH];          // [b][24 pg][HW][8] fp16
__device__ __half g_v  [(size_t)NB * HW * CCH];          // [b][24 pg][HW][8] fp16
__device__ __half g_at [(size_t)NB * HW * CCH];          // [b][pix][192] fp16

// ============================================================================
// Weight prep: fp32 -> fp16
// ============================================================================
__global__ void prep_weights(const float* __restrict__ w_qkv,
                             const float* __restrict__ w_out) {
    const int i = blockIdx.x * 256 + threadIdx.x;
    const int total = (576 + 192) * CCH;
    if (i >= total) return;
    const float v = (i < 576 * CCH) ? w_qkv[i] : w_out[i - 576 * CCH];
    g_w16[i] = __float2half_rn(v);
}

// ============================================================================
// Transpose: x[b][192][HW] fp32 -> g_x16[b][pix][192] fp16
// ============================================================================
__global__ void transpose_k(const float* __restrict__ x) {
    __shared__ float tile[32][33];
    const int b  = blockIdx.z;
    const int p0 = blockIdx.x * 32, c0 = blockIdx.y * 32;
    const float* xb = x + (size_t)b * CCH * HW;
    __half* tb = g_x16 + (size_t)b * HW * CCH;
    const int tx = threadIdx.x, ty = threadIdx.y;
    #pragma unroll
    for (int j = 0; j < 32; j += 8)
        tile[ty + j][tx] = xb[(size_t)(c0 + ty + j) * HW + p0 + tx];
    __syncthreads();
    #pragma unroll
    for (int j = 0; j < 32; j += 8)
        tb[(size_t)(p0 + ty + j) * CCH + c0 + tx] = __float2half_rn(tile[tx][ty + j]);
}

// ============================================================================
// fp16 GEMM via mma.sync.m16n8k16: C[m][n] = sum_k A[m][k]*B[n][k]
//   A: [M][192] fp16 per-batch (stride HW*CCH), B: [Ntot][192] fp16.
//   Tile M=128, N=64, K staged 3x64, 8 warps, warp tile 32x32.
//   MODE=1: C fp32 [n][HW] channel-major (d_out).
//   MODE=2: qkv epilogue -> g_q (fp32 d4), g_k/g_v (fp16 d8) via smem staging.
// ============================================================================
#define RS    144                      // smem tile row stride bytes
#define SM_A  0
#define SM_B  (128 * RS)               // 18432
#define SM_GTOT 38912                  // q staging: 128 rows * 304B

__device__ __forceinline__ void mma16816(float* c, const uint32_t* a, const uint32_t* b) {
    asm volatile(
        "mma.sync.aligned.m16n8k16.row.col.f32.f16.f16.f32 "
        "{%0,%1,%2,%3}, {%4,%5,%6,%7}, {%8,%9}, {%0,%1,%2,%3};"
        : "+f"(c[0]), "+f"(c[1]), "+f"(c[2]), "+f"(c[3])
        : "r"(a[0]), "r"(a[1]), "r"(a[2]), "r"(a[3]), "r"(b[0]), "r"(b[1]));
}

template<int MODE>
__global__ __launch_bounds__(256, 2)
void mma_gemm(const __half* __restrict__ A, const __half* __restrict__ B,
              float* __restrict__ Cout)
{
    extern __shared__ char smem[];
    const int t    = threadIdx.x;
    const int wid  = t >> 5, lane = t & 31;
    const int gid  = lane >> 2, tig = lane & 3;
    const int wm   = wid & 3, wn = wid >> 2;
    const int m0   = blockIdx.y * 128;
    const int n0   = blockIdx.x * 64;
    const int b    = blockIdx.z;

    const __half* Ab = A + (size_t)b * HW * CCH + (size_t)m0 * CCH;

    float acc[2][4][4];
    #pragma unroll
    for (int mi = 0; mi < 2; mi++)
        #pragma unroll
        for (int ni = 0; ni < 4; ni++)
            #pragma unroll
            for (int j = 0; j < 4; j++) acc[mi][ni][j] = 0.f;

    #pragma unroll 1
    for (int s = 0; s < 3; s++) {
        const int k0 = s * 64;
        #pragma unroll
        for (int i = 0; i < 4; i++) {       // A: 128x64 fp16 = 1024 16B chunks
            const int idx = t + i * 256;
            const int row = idx >> 3, c8 = (idx & 7) * 8;
            *(uint4*)(smem + SM_A + row * RS + c8 * 2) =
                *(const uint4*)(Ab + (size_t)row * CCH + k0 + c8);
        }
        #pragma unroll
        for (int i = 0; i < 2; i++) {       // B: 64x64 fp16 = 512 chunks
            const int idx = t + i * 256;
            const int row = idx >> 3, c8 = (idx & 7) * 8;
            *(uint4*)(smem + SM_B + row * RS + c8 * 2) =
                *(const uint4*)(B + (size_t)(n0 + row) * CCH + k0 + c8);
        }
        __syncthreads();

        #pragma unroll
        for (int kk = 0; kk < 4; kk++) {
            const uint32_t cb = kk * 32 + tig * 4;
            uint32_t ah[2][4], bh[4][2];
            #pragma unroll
            for (int mi = 0; mi < 2; mi++) {
                const uint32_t r0 = (wm * 32 + mi * 16 + gid) * RS + cb;
                ah[mi][0] = *(const uint32_t*)(smem + SM_A + r0);
                ah[mi][1] = *(const uint32_t*)(smem + SM_A + r0 + 8 * RS);
                ah[mi][2] = *(const uint32_t*)(smem + SM_A + r0 + 16);
                ah[mi][3] = *(const uint32_t*)(smem + SM_A + r0 + 8 * RS + 16);
            }
            #pragma unroll
            for (int ni = 0; ni < 4; ni++) {
                const uint32_t rn = (wn * 32 + ni * 8 + gid) * RS + cb;
                bh[ni][0] = *(const uint32_t*)(smem + SM_B + rn);
                bh[ni][1] = *(const uint32_t*)(smem + SM_B + rn + 16);
            }
            #pragma unroll
            for (int mi = 0; mi < 2; mi++)
                #pragma unroll
                for (int ni = 0; ni < 4; ni++)
                    mma16816(acc[mi][ni], ah[mi], bh[ni]);
        }
        __syncthreads();
    }

    if (MODE == 1) {
        // direct channel-major fp32 stores: Cout[b][col][HW]
        float* Cb = Cout + (size_t)b * CCH * HW;
        #pragma unroll
        for (int mi = 0; mi < 2; mi++) {
            const int row = m0 + wm * 32 + mi * 16 + gid;
            #pragma unroll
            for (int ni = 0; ni < 4; ni++) {
                const int col = n0 + wn * 32 + ni * 8 + 2 * tig;
                Cb[(size_t)col       * HW + row]     = acc[mi][ni][0];
                Cb[(size_t)(col + 1) * HW + row]     = acc[mi][ni][1];
                Cb[(size_t)col       * HW + row + 8] = acc[mi][ni][2];
                Cb[(size_t)(col + 1) * HW + row + 8] = acc[mi][ni][3];
            }
        }
    } else {
        // qkv epilogue via smem staging. n-tile type: 0=q, 1=k, 2=v.
        const int type = n0 / 192;
        if (type == 0) {
            float* st = (float*)smem;           // stride 76 floats (304B)
            #pragma unroll
            for (int mi = 0; mi < 2; mi++) {
                const int rl = wm * 32 + mi * 16 + gid;
                #pragma unroll
                for (int ni = 0; ni < 4; ni++) {
                    const int cl = wn * 32 + ni * 8 + 2 * tig;
                    *(float2*)&st[rl * 76 + cl] =
                        make_float2(acc[mi][ni][0], acc[mi][ni][1]);
                    *(float2*)&st[(rl + 8) * 76 + cl] =
                        make_float2(acc[mi][ni][2], acc[mi][ni][3]);
                }
            }
            __syncthreads();
            #pragma unroll
            for (int i = 0; i < 8; i++) {       // 16 pgs x 128 rows
                const int idx = i * 256 + t;
                const int r = idx & 127, pg = idx >> 7;
                uint4 val = *(uint4*)&st[r * 76 + pg * 4];
                *(uint4*)&g_q[(((size_t)b * 48 + n0 / 4 + pg) * HW + m0 + r) * 4] = val;
            }
        } else {
            __half* st = (__half*)smem;         // stride 72 halves (144B)
            #pragma unroll
            for (int mi = 0; mi < 2; mi++) {
                const int rl = wm * 32 + mi * 16 + gid;
                #pragma unroll
                for (int ni = 0; ni < 4; ni++) {
                    const int cl = wn * 32 + ni * 8 + 2 * tig;
                    *(__half2*)&st[rl * 72 + cl] =
                        __floats2half2_rn(acc[mi][ni][0], acc[mi][ni][1]);
                    *(__half2*)&st[(rl + 8) * 72 + cl] =
                        __floats2half2_rn(acc[mi][ni][2], acc[mi][ni][3]);
                }
            }
            __syncthreads();
            __half* dst = (type == 1) ? g_k : g_v;
            const int pgb = (n0 - type * 192) / 8;
            #pragma unroll
            for (int i = 0; i < 4; i++) {       // 8 pgs x 128 rows
                const int idx = i * 256 + t;
                const int r = idx & 127, pg = idx >> 7;
                uint4 val = *(uint4*)&st[r * 72 + pg * 8];
                *(uint4*)&dst[(((size_t)b * 24 + pgb + pg) * HW + m0 + r) * 8] = val;
            }
        }
    }
}

// ============================================================================
// Neighborhood attention: q fp32 d4-packed, k/v fp16 d8-packed.
// ============================================================================
template<int K, int DIL>
__device__ __forceinline__ void natt_body(const float* __restrict__ sbias,
                                          int head, int b)
{
    const int w   = blockIdx.x * 32 + threadIdx.x;
    const int h   = blockIdx.y * 4  + threadIdx.y;
    const int pix = h * IMG_W + w;

    const float*  qb = g_q + (((size_t)b * 48 + head * 8) * HW + pix) * 4;
    const __half* kb = g_k + ((size_t)b * 24 + head * 4) * HW * 8;
    const __half* vb = g_v + ((size_t)b * 24 + head * 4) * HW * 8;
    const float scale = 0.17677669529663689f;   // 1/sqrt(32)

    float4 q[8];
    #pragma unroll
    for (int i = 0; i < 8; i++) {
        float4 tq = *(const float4*)(qb + (size_t)i * HW * 4);
        q[i] = make_float4(tq.x * scale, tq.y * scale, tq.z * scale, tq.w * scale);
    }

    float4 acc[8];
    #pragma unroll
    for (int i = 0; i < 8; i++) acc[i] = make_float4(0.f, 0.f, 0.f, 0.f);
    float l = 0.f;

    #pragma unroll 1
    for (int di = 0; di < K; di++) {
        const int hh = h + (di - K / 2) * DIL;
        const bool rok = ((unsigned)hh < IMG_H);
        #pragma unroll
        for (int dj = 0; dj < K; dj++) {
            const int ww = w + (dj - K / 2) * DIL;
            const bool ok = rok && ((unsigned)ww < IMG_W);
            const int off = hh * IMG_W + ww;
            float s = 0.f;
            if (ok) {
                const __half* kp = kb + (size_t)off * 8;
                #pragma unroll
                for (int j = 0; j < 4; j++) {
                    uint4 raw = *(const uint4*)(kp + (size_t)j * HW * 8);
                    float2 p0 = __half22float2(*(const __half2*)&raw.x);
                    float2 p1 = __half22float2(*(const __half2*)&raw.y);
                    float2 p2 = __half22float2(*(const __half2*)&raw.z);
                    float2 p3 = __half22float2(*(const __half2*)&raw.w);
                    s += q[2*j].x   * p0.x + q[2*j].y   * p0.y
                       + q[2*j].z   * p1.x + q[2*j].w   * p1.y
                       + q[2*j+1].x * p2.x + q[2*j+1].y * p2.y
                       + q[2*j+1].z * p3.x + q[2*j+1].w * p3.y;
                }
            }
            const float e = __expf(s + sbias[di * K + dj]);
            l += e;
            if (ok) {
                const __half* vp = vb + (size_t)off * 8;
                #pragma unroll
                for (int j = 0; j < 4; j++) {
                    uint4 raw = *(const uint4*)(vp + (size_t)j * HW * 8);
                    float2 p0 = __half22float2(*(const __half2*)&raw.x);
                    float2 p1 = __half22float2(*(const __half2*)&raw.y);
                    float2 p2 = __half22float2(*(const __half2*)&raw.z);
                    float2 p3 = __half22float2(*(const __half2*)&raw.w);
                    acc[2*j].x   += e * p0.x; acc[2*j].y   += e * p0.y;
                    acc[2*j].z   += e * p1.x; acc[2*j].w   += e * p1.y;
                    acc[2*j+1].x += e * p2.x; acc[2*j+1].y += e * p2.y;
                    acc[2*j+1].z += e * p3.x; acc[2*j+1].w += e * p3.y;
                }
            }
        }
    }

    const float il = 1.f / l;
    const size_t ob = ((size_t)b * HW + pix) * CCH + head * 32;
    #pragma unroll
    for (int j = 0; j < 4; j++) {
        __half2 h0 = __floats2half2_rn(acc[2*j].x   * il, acc[2*j].y   * il);
        __half2 h1 = __floats2half2_rn(acc[2*j].z   * il, acc[2*j].w   * il);
        __half2 h2 = __floats2half2_rn(acc[2*j+1].x * il, acc[2*j+1].y * il);
        __half2 h3 = __floats2half2_rn(acc[2*j+1].z * il, acc[2*j+1].w * il);
        uint4 val;
        val.x = *(uint32_t*)&h0; val.y = *(uint32_t*)&h1;
        val.z = *(uint32_t*)&h2; val.w = *(uint32_t*)&h3;
        *(uint4*)&g_at[ob + j * 8] = val;
    }
}

__global__ __launch_bounds__(128, 6)
void natt_all(const float* __restrict__ b0, const float* __restrict__ b1,
              const float* __restrict__ b2, const float* __restrict__ b3,
              const float* __restrict__ b4, const float* __restrict__ b5)
{
    __shared__ float sb[81];
    const int z = blockIdx.z;
    const int head = z % 6;
    const int b    = z / 6;
    const float* bp;
    int k2;
    switch (head) {
        case 0: bp = b0; k2 = 9;  break;
        case 1: bp = b1; k2 = 25; break;
        case 2: bp = b2; k2 = 49; break;
        case 3: bp = b3; k2 = 49; break;
        case 4: bp = b4; k2 = 81; break;
        default: bp = b5; k2 = 81; break;
    }
    const int t = threadIdx.y * 32 + threadIdx.x;
    if (t < k2) sb[t] = bp[t];
    __syncthreads();
    switch (head) {
        case 0: natt_body<3, 1>(sb, 0, b); break;
        case 1: natt_body<5, 2>(sb, 1, b); break;
        case 2: natt_body<7, 1>(sb, 2, b); break;
        case 3: natt_body<7, 3>(sb, 3, b); break;
        case 4: natt_body<9, 1>(sb, 4, b); break;
        case 5: natt_body<9, 2>(sb, 5, b); break;
    }
}

// ============================================================================
extern "C" void kernel_launch(void* const* d_in, const int* in_sizes, int n_in,
                              void* d_out, int out_size)
{
    (void)in_sizes; (void)n_in; (void)out_size;
    const float* x     = (const float*)d_in[0];
    const float* w_qkv = (const float*)d_in[1];
    const float* w_out = (const float*)d_in[2];
    const float* b0 = (const float*)d_in[3];
    const float* b1 = (const float*)d_in[4];
    const float* b2 = (const float*)d_in[5];
    const float* b3 = (const float*)d_in[6];
    const float* b4 = (const float*)d_in[7];
    const float* b5 = (const float*)d_in[8];

    __half *x16, *w16, *at16;
    cudaGetSymbolAddress((void**)&x16,  g_x16);
    cudaGetSymbolAddress((void**)&w16,  g_w16);
    cudaGetSymbolAddress((void**)&at16, g_at);

    cudaFuncSetAttribute(mma_gemm<1>, cudaFuncAttributeMaxDynamicSharedMemorySize, SM_GTOT);
    cudaFuncSetAttribute(mma_gemm<2>, cudaFuncAttributeMaxDynamicSharedMemorySize, SM_GTOT);

    prep_weights<<<(768 * CCH + 255) / 256, 256>>>(w_qkv, w_out);
    transpose_k<<<dim3(HW / 32, CCH / 32, NB), dim3(32, 8)>>>(x);

    // qkv = x16 @ w_qkv^T  -> g_q / g_k / g_v (packed layouts)
    mma_gemm<2><<<dim3(576 / 64, HW / 128, NB), 256, SM_GTOT>>>(x16, w16, nullptr);

    natt_all<<<dim3(IMG_W / 32, IMG_H / 4, NB * 6), dim3(32, 4)>>>(
        b0, b1, b2, b3, b4, b5);

    // d_out[b][ch][pix] = (attn @ w_out^T)^T
    mma_gemm<1><<<dim3(CCH / 64, HW / 128, NB), 256, SM_GTOT>>>(
        at16, w16 + 576 * CCH, (float*)d_out);
}